// round 13
// baseline (speedup 1.0000x reference)
#include <cuda_runtime.h>
#include <cuda_bf16.h>
#include <stdint.h>
#include <math.h>

#define BB 4
#define TT 2048
#define DD 1024
#define HH 16
#define DH 64
#define BT (BB*TT)

// ---------------- scratch ----------------------------------------------------
__device__ float g_q [BT*DD];
__device__ float g_k [BT*DD];
__device__ float g_v [BT*DD];
__device__ __nv_bfloat16 g_aohi[BT*DD];
__device__ __nv_bfloat16 g_aolo[BT*DD];
__device__ __nv_bfloat16 g_qhi [BT*DD];
__device__ __nv_bfloat16 g_qlo [BT*DD];
__device__ __nv_bfloat16 g_khi [BT*DD];
__device__ __nv_bfloat16 g_klo [BT*DD];
__device__ __nv_bfloat16 g_vhi [BT*DD];
__device__ __nv_bfloat16 g_vlo [BT*DD];
// int8 quantized activations / weights
__device__ signed char g_x1 [BT*DD];
__device__ signed char g_x2 [BT*DD];
__device__ float       g_sx [BT];
__device__ signed char g_ao1[BT*DD];
__device__ signed char g_ao2[BT*DD];
__device__ float       g_sao[BT];
__device__ signed char g_wt1[4*DD*DD];   // [w*1024+n][k]
__device__ signed char g_wt2[4*DD*DD];
__device__ int         g_swi[4*DD];      // col abs-max as float bits
__device__ float       g_swf[4*DD];      // scale = max/127

// ---------------- PTX helpers ------------------------------------------------
static __device__ __forceinline__ uint32_t s2u(const void* p){
    uint32_t a;
    asm("{ .reg .u64 t; cvta.to.shared.u64 t, %1; cvt.u32.u64 %0, t; }" : "=r"(a) : "l"(p));
    return a;
}
static __device__ __forceinline__ void cpa16(uint32_t dst, const void* src){
    asm volatile("cp.async.cg.shared.global [%0], [%1], 16;" :: "r"(dst), "l"(src));
}
#define CP_COMMIT()  asm volatile("cp.async.commit_group;" ::: "memory")
#define CP_WAIT1()   asm volatile("cp.async.wait_group 1;" ::: "memory")
#define CP_WAIT0()   asm volatile("cp.async.wait_group 0;" ::: "memory")

#define LDSM4(r, addr) \
    asm volatile("ldmatrix.sync.aligned.m8n8.x4.shared.b16 {%0,%1,%2,%3}, [%4];" \
        : "=r"((r)[0]), "=r"((r)[1]), "=r"((r)[2]), "=r"((r)[3]) : "r"(addr))
#define LDSM4T(r, addr) \
    asm volatile("ldmatrix.sync.aligned.m8n8.x4.trans.shared.b16 {%0,%1,%2,%3}, [%4];" \
        : "=r"((r)[0]), "=r"((r)[1]), "=r"((r)[2]), "=r"((r)[3]) : "r"(addr))
#define MMA16816(d, a, b) \
    asm volatile("mma.sync.aligned.m16n8k16.row.col.f32.bf16.bf16.f32 " \
        "{%0,%1,%2,%3}, {%4,%5,%6,%7}, {%8,%9}, {%0,%1,%2,%3};" \
        : "+f"((d)[0]), "+f"((d)[1]), "+f"((d)[2]), "+f"((d)[3]) \
        : "r"((a)[0]), "r"((a)[1]), "r"((a)[2]), "r"((a)[3]), \
          "r"((b)[0]), "r"((b)[1]))
#define IMMA16832(d, a, b) \
    asm volatile("mma.sync.aligned.m16n8k32.row.col.s32.s8.s8.s32 " \
        "{%0,%1,%2,%3}, {%4,%5,%6,%7}, {%8,%9}, {%0,%1,%2,%3};" \
        : "+r"((d)[0]), "+r"((d)[1]), "+r"((d)[2]), "+r"((d)[3]) \
        : "r"((a)[0]), "r"((a)[1]), "r"((a)[2]), "r"((a)[3]), \
          "r"((b)[0]), "r"((b)[1]))

static __device__ __forceinline__ uint32_t pack_bf16(float x, float y){
    __nv_bfloat162 t = __floats2bfloat162_rn(x, y);
    return *(uint32_t*)&t;
}

// ---------------- weight quantization ----------------------------------------
__global__ void k_colmax(const float* __restrict__ Wq, const float* __restrict__ Wk,
                         const float* __restrict__ Wv, const float* __restrict__ Wo)
{
    __shared__ float red[256];
    int w = blockIdx.y;
    const float* W = (w == 0) ? Wq : (w == 1) ? Wk : (w == 2) ? Wv : Wo;
    int tx = threadIdx.x & 31, ty = threadIdx.x >> 5;
    int col = blockIdx.x * 32 + tx;
    float m = 0.f;
    for (int k = ty; k < DD; k += 8)
        m = fmaxf(m, fabsf(W[(size_t)k * DD + col]));
    red[threadIdx.x] = m;
    __syncthreads();
    if (ty == 0) {
        #pragma unroll
        for (int i = 1; i < 8; i++) m = fmaxf(m, red[i * 32 + tx]);
        atomicMax(&g_swi[w * DD + col], __float_as_int(m));
    }
}

__global__ void k_wquant(const float* __restrict__ Wq, const float* __restrict__ Wk,
                         const float* __restrict__ Wv, const float* __restrict__ Wo)
{
    __shared__ float t[32][33];
    int w = blockIdx.z;
    const float* W = (w == 0) ? Wq : (w == 1) ? Wk : (w == 2) ? Wv : Wo;
    int tx = threadIdx.x, ty = threadIdx.y;
    #pragma unroll
    for (int i = 0; i < 4; i++) {
        int k = blockIdx.y * 32 + ty + i * 8;
        int n = blockIdx.x * 32 + tx;
        t[ty + i * 8][tx] = W[(size_t)k * DD + n];
    }
    __syncthreads();
    #pragma unroll
    for (int i = 0; i < 4; i++) {
        int n = blockIdx.x * 32 + ty + i * 8;
        int k = blockIdx.y * 32 + tx;
        float s = fmaxf(__int_as_float(g_swi[w * DD + n]), 1e-20f) / 127.0f;
        if (tx == 0 && blockIdx.y == 0) g_swf[w * DD + n] = s;
        float v = t[tx][ty + i * 8];
        float q1 = rintf(v / s);
        float q2 = rintf((v - q1 * s) * (254.0f / s));
        g_wt1[(size_t)(w * DD + n) * DD + k] = (signed char)(int)q1;
        g_wt2[(size_t)(w * DD + n) * DD + k] = (signed char)(int)q2;
    }
}

// ---------------- activation quantization (one warp per row) -----------------
__global__ void k_quant(const float* __restrict__ x, int mode)
{
    int wid = threadIdx.x >> 5, lane = threadIdx.x & 31;
    int row = blockIdx.x * 8 + wid;
    signed char* o1 = mode ? g_ao1 : g_x1;
    signed char* o2 = mode ? g_ao2 : g_x2;
    float* os = mode ? g_sao : g_sx;

    float v[32];
    size_t base = (size_t)row * DD + lane * 32;
    if (mode == 0) {
        #pragma unroll
        for (int j = 0; j < 8; j++) {
            float4 f = *(const float4*)(x + base + j * 4);
            v[j*4] = f.x; v[j*4+1] = f.y; v[j*4+2] = f.z; v[j*4+3] = f.w;
        }
    } else {
        #pragma unroll
        for (int j = 0; j < 8; j++) {
            uint2 h = *(const uint2*)(g_aohi + base + j * 4);
            uint2 l = *(const uint2*)(g_aolo + base + j * 4);
            __nv_bfloat162 h0 = *(__nv_bfloat162*)&h.x, h1 = *(__nv_bfloat162*)&h.y;
            __nv_bfloat162 l0 = *(__nv_bfloat162*)&l.x, l1 = *(__nv_bfloat162*)&l.y;
            v[j*4]   = __bfloat162float(h0.x) + __bfloat162float(l0.x);
            v[j*4+1] = __bfloat162float(h0.y) + __bfloat162float(l0.y);
            v[j*4+2] = __bfloat162float(h1.x) + __bfloat162float(l1.x);
            v[j*4+3] = __bfloat162float(h1.y) + __bfloat162float(l1.y);
        }
    }
    float m = 0.f;
    #pragma unroll
    for (int j = 0; j < 32; j++) m = fmaxf(m, fabsf(v[j]));
    #pragma unroll
    for (int o = 16; o; o >>= 1) m = fmaxf(m, __shfl_xor_sync(0xffffffffu, m, o));
    float s = fmaxf(m, 1e-20f) / 127.0f;
    if (lane == 0) os[row] = s;
    float inv = 1.0f / s;
    uint32_t w1[8], w2[8];
    #pragma unroll
    for (int j = 0; j < 8; j++) {
        uint32_t a = 0, b = 0;
        #pragma unroll
        for (int e = 0; e < 4; e++) {
            float q1 = rintf(v[j*4+e] * inv);
            float q2 = rintf((v[j*4+e] - q1 * s) * 254.0f * inv);
            a |= ((uint32_t)((int)q1 & 255)) << (e * 8);
            b |= ((uint32_t)((int)q2 & 255)) << (e * 8);
        }
        w1[j] = a; w2[j] = b;
    }
    *(uint4*)(o1 + base)      = make_uint4(w1[0], w1[1], w1[2], w1[3]);
    *(uint4*)(o1 + base + 16) = make_uint4(w1[4], w1[5], w1[6], w1[7]);
    *(uint4*)(o2 + base)      = make_uint4(w2[0], w2[1], w2[2], w2[3]);
    *(uint4*)(o2 + base + 16) = make_uint4(w2[4], w2[5], w2[6], w2[7]);
}

// ---------------- int8 2-slice GEMM -------------------------------------------
// Block 128x128, BK=64, 3-stage cp.async, 8 warps (64x32), 3 IMMAs per tile-k32.
// Rows 64B, swizzle chunk ^= (row>>1)&3 (validated conflict-free).
#define TILEB (128*64)
#define STGB  (4*TILEB)             // A1, A2, B1, B2
#define NSTG  3
#define GSMEM (NSTG*STGB)           // 98304

__global__ void __launch_bounds__(256, 1)
k_gemm(int asel, float* __restrict__ Cext, int wsel)
{
    extern __shared__ char smem[];
    const uint32_t sb0 = s2u(smem);
    const int tid  = threadIdx.x;
    const int lane = tid & 31, wid = tid >> 5;
    const int wm = wid >> 2, wn = wid & 3;
    const int m0 = blockIdx.y * 128, n0 = blockIdx.x * 128;

    const signed char* A1 = asel ? g_ao1 : g_x1;
    const signed char* A2 = asel ? g_ao2 : g_x2;
    const float*       sA = asel ? g_sao : g_sx;
    const int w = (wsel < 0) ? (int)blockIdx.z : wsel;
    float* C = (wsel < 0) ? (blockIdx.z == 0 ? g_q : (blockIdx.z == 1 ? g_k : g_v)) : Cext;
    const signed char* B1 = g_wt1 + (size_t)w * DD * DD;
    const signed char* B2 = g_wt2 + (size_t)w * DD * DD;
    const float*       sB = g_swf + (size_t)w * DD;

    auto load_stage = [&](int s, int kc) {
        const uint32_t st = sb0 + s * STGB;
        const int k0 = kc * 64;
        #pragma unroll
        for (int j = 0; j < 2; j++) {
            int e   = tid + j * 256;        // 0..511: 128 rows x 4 chunks
            int row = e >> 2, c4 = e & 3;
            size_t ga = (size_t)(m0 + row) * DD + k0 + c4 * 16;
            size_t gb = (size_t)(n0 + row) * DD + k0 + c4 * 16;
            uint32_t so = row * 64 + ((c4 ^ ((row >> 1) & 3)) << 4);
            cpa16(st + so,             A1 + ga);
            cpa16(st + TILEB + so,     A2 + ga);
            cpa16(st + 2*TILEB + so,   B1 + gb);
            cpa16(st + 3*TILEB + so,   B2 + gb);
        }
        CP_COMMIT();
    };

    uint32_t acc1[4][4][4] = {};
    uint32_t acc2[4][4][4] = {};
    const int lrow = lane & 15;
    const int swl  = (lrow >> 1) & 3;
    const int lhalf = lane >> 4;

    load_stage(0, 0);
    load_stage(1, 1);

    for (int kc = 0; kc < 16; kc++) {
        CP_WAIT1();
        __syncthreads();
        if (kc + 2 < 16) load_stage((kc + 2) % NSTG, kc + 2);
        else             CP_COMMIT();

        const uint32_t sA_ = sb0 + (kc % NSTG) * STGB;
        const uint32_t sB_ = sA_ + 2 * TILEB;

        #pragma unroll
        for (int kk = 0; kk < 2; kk++) {
            const int chunk = kk * 2 + lhalf;
            const uint32_t soff = lrow * 64 + ((chunk ^ swl) << 4);
            uint32_t a1[4][4], a2[4][4];
            #pragma unroll
            for (int i = 0; i < 4; i++) {
                uint32_t ad = sA_ + (wm * 64 + i * 16) * 64 + soff;
                LDSM4(a1[i], ad);
                LDSM4(a2[i], ad + TILEB);
            }
            uint32_t b1[4][2], b2[4][2];
            #pragma unroll
            for (int g = 0; g < 2; g++) {
                uint32_t bd = sB_ + (wn * 32 + g * 16) * 64 + soff;
                uint32_t r[4];
                LDSM4(r, bd);
                b1[g*2][0] = r[0]; b1[g*2+1][0] = r[1];
                b1[g*2][1] = r[2]; b1[g*2+1][1] = r[3];
                LDSM4(r, bd + TILEB);
                b2[g*2][0] = r[0]; b2[g*2+1][0] = r[1];
                b2[g*2][1] = r[2]; b2[g*2+1][1] = r[3];
            }
            #pragma unroll
            for (int i = 0; i < 4; i++)
                #pragma unroll
                for (int j = 0; j < 4; j++) {
                    IMMA16832(acc1[i][j], a1[i], b1[j]);
                    IMMA16832(acc2[i][j], a1[i], b2[j]);
                    IMMA16832(acc2[i][j], a2[i], b1[j]);
                }
        }
    }

    const float INV254 = 1.0f / 254.0f;
    #pragma unroll
    for (int i = 0; i < 4; i++) {
        int row = m0 + wm * 64 + i * 16 + (lane >> 2);
        float s0 = sA[row], s8 = sA[row + 8];
        #pragma unroll
        for (int j = 0; j < 4; j++) {
            int col = n0 + wn * 32 + j * 8 + (lane & 3) * 2;
            float t0 = sB[col], t1 = sB[col + 1];
            float c00 = s0 * t0 * ((float)(int)acc1[i][j][0] + (float)(int)acc2[i][j][0] * INV254);
            float c01 = s0 * t1 * ((float)(int)acc1[i][j][1] + (float)(int)acc2[i][j][1] * INV254);
            float c10 = s8 * t0 * ((float)(int)acc1[i][j][2] + (float)(int)acc2[i][j][2] * INV254);
            float c11 = s8 * t1 * ((float)(int)acc1[i][j][3] + (float)(int)acc2[i][j][3] * INV254);
            *(float2*)(C + (size_t)row * DD + col)       = make_float2(c00, c01);
            *(float2*)(C + (size_t)(row + 8) * DD + col) = make_float2(c10, c11);
        }
    }
}

// ---------------- RoPE + hi/lo conversion (unchanged) ------------------------
__global__ void k_rope_cvt(const float* __restrict__ cosT, const float* __restrict__ sinT)
{
    int n = blockIdx.x * blockDim.x + threadIdx.x;
    int y = blockIdx.y;
    const float* src = (y == 0) ? g_q : (y == 1) ? g_k : g_v;
    __nv_bfloat16* hi = (y == 0) ? g_qhi : (y == 1) ? g_khi : g_vhi;
    __nv_bfloat16* lo = (y == 0) ? g_qlo : (y == 1) ? g_klo : g_vlo;
    int i4   = (n & 7) * 4;
    int rest = n >> 3;
    int h    = rest & (HH - 1);
    int bt   = rest >> 4;
    int t    = bt & (TT - 1);

    size_t off = (size_t)bt * DD + h * DH;
    float4 x0 = *(const float4*)(src + off + i4);
    float4 x1 = *(const float4*)(src + off + i4 + 32);
    float4 y0, y1;
    if (y < 2) {
        float4 c0 = *(const float4*)(cosT + t * DH + i4);
        float4 s0 = *(const float4*)(sinT + t * DH + i4);
        float4 c1 = *(const float4*)(cosT + t * DH + i4 + 32);
        float4 s1 = *(const float4*)(sinT + t * DH + i4 + 32);
        y0.x = x0.x*c0.x - x1.x*s0.x;  y0.y = x0.y*c0.y - x1.y*s0.y;
        y0.z = x0.z*c0.z - x1.z*s0.z;  y0.w = x0.w*c0.w - x1.w*s0.w;
        y1.x = x1.x*c1.x + x0.x*s1.x;  y1.y = x1.y*c1.y + x0.y*s1.y;
        y1.z = x1.z*c1.z + x0.z*s1.z;  y1.w = x1.w*c1.w + x0.w*s1.w;
        if (y == 0) {
            y0.x *= 0.125f; y0.y *= 0.125f; y0.z *= 0.125f; y0.w *= 0.125f;
            y1.x *= 0.125f; y1.y *= 0.125f; y1.z *= 0.125f; y1.w *= 0.125f;
        }
    } else { y0 = x0; y1 = x1; }

    uint2 h0, h1, l0, l1;
    h0.x = pack_bf16(y0.x, y0.y); h0.y = pack_bf16(y0.z, y0.w);
    h1.x = pack_bf16(y1.x, y1.y); h1.y = pack_bf16(y1.z, y1.w);
    __nv_bfloat162 t0 = *(__nv_bfloat162*)&h0.x, t1 = *(__nv_bfloat162*)&h0.y;
    __nv_bfloat162 t2 = *(__nv_bfloat162*)&h1.x, t3 = *(__nv_bfloat162*)&h1.y;
    l0.x = pack_bf16(y0.x - __bfloat162float(t0.x), y0.y - __bfloat162float(t0.y));
    l0.y = pack_bf16(y0.z - __bfloat162float(t1.x), y0.w - __bfloat162float(t1.y));
    l1.x = pack_bf16(y1.x - __bfloat162float(t2.x), y1.y - __bfloat162float(t2.y));
    l1.y = pack_bf16(y1.z - __bfloat162float(t3.x), y1.w - __bfloat162float(t3.y));
    *(uint2*)(hi + off + i4)      = h0;
    *(uint2*)(hi + off + i4 + 32) = h1;
    *(uint2*)(lo + off + i4)      = l0;
    *(uint2*)(lo + off + i4 + 32) = l1;
}

// ---------------- Flash attention (unchanged, swizzled bf16) -----------------
#define FQT   (128*128)
#define FKT   (64*128)
#define FSTG  (4*FKT)
#define FSMEM (2*FQT + 2*FSTG)      // 98304

__global__ void __launch_bounds__(256, 1) k_flash_mma()
{
    extern __shared__ char fsm[];
    const uint32_t sb = s2u(fsm);
    const int tid = threadIdx.x, lane = tid & 31, wid = tid >> 5;
    const int qt = (gridDim.x - 1) - blockIdx.x;
    const int h = blockIdx.y, b = blockIdx.z;
    const int qrow0 = qt * 128;
    const int nkt = 2 * qt + 2;
    const int lrow = lane & 15;
    const int sw7  = lane & 7;
    const int lhalf = lane >> 4;

    {
        #pragma unroll
        for (int j = 0; j < 4; j++) {
            int e = tid + j * 256;
            int row = e >> 3, c8 = e & 7;
            size_t g = (size_t)(b * TT + qrow0 + row) * DD + h * DH + c8 * 8;
            uint32_t so = row * 128 + ((c8 ^ (row & 7)) << 4);
            cpa16(sb + so,       g_qhi + g);
            cpa16(sb + FQT + so, g_qlo + g);
        }
    }
    auto load_kv = [&](int kt) {
        const uint32_t st = sb + 2 * FQT + (kt & 1) * FSTG;
        #pragma unroll
        for (int j = 0; j < 2; j++) {
            int e = tid + j * 256;
            int row = e >> 3, c8 = e & 7;
            size_t g = (size_t)(b * TT + kt * 64 + row) * DD + h * DH + c8 * 8;
            uint32_t so = row * 128 + ((c8 ^ (row & 7)) << 4);
            cpa16(st + so,         g_khi + g);
            cpa16(st + FKT + so,   g_klo + g);
            cpa16(st + 2*FKT + so, g_vhi + g);
            cpa16(st + 3*FKT + so, g_vlo + g);
        }
    };
    load_kv(0);
    CP_COMMIT();

    uint32_t qhi[4][4], qlo[4][4];
    float oacc[8][4] = {};
    float m0 = -INFINITY, m1 = -INFINITY, l0 = 0.f, l1 = 0.f;
    const int qr0 = qrow0 + wid * 16 + (lane >> 2);
    const int qr1 = qr0 + 8;

    for (int kt = 0; kt < nkt; kt++) {
        CP_WAIT0();
        __syncthreads();
        if (kt == 0) {
            #pragma unroll
            for (int kf = 0; kf < 4; kf++) {
                int chunk = kf * 2 + lhalf;
                uint32_t ad = sb + (wid * 16 + lrow) * 128 + ((chunk ^ sw7) << 4);
                LDSM4(qhi[kf], ad);
                LDSM4(qlo[kf], ad + FQT);
            }
        }
        if (kt + 1 < nkt) { load_kv(kt + 1); CP_COMMIT(); }

        const bool active = (kt * 64) <= (qrow0 + wid * 16 + 15);
        if (active) {
            const uint32_t Kb = sb + 2 * FQT + (kt & 1) * FSTG;
            const uint32_t Vb = Kb + 2 * FKT;

            float sacc[8][4] = {};
            #pragma unroll
            for (int kf = 0; kf < 4; kf++) {
                const int chunk = kf * 2 + lhalf;
                uint32_t bh[8][2], bl[8][2];
                #pragma unroll
                for (int nt2 = 0; nt2 < 4; nt2++) {
                    uint32_t ad = Kb + (nt2 * 16 + lrow) * 128 + ((chunk ^ sw7) << 4);
                    uint32_t r[4];
                    LDSM4(r, ad);
                    bh[nt2*2][0] = r[0]; bh[nt2*2+1][0] = r[1];
                    bh[nt2*2][1] = r[2]; bh[nt2*2+1][1] = r[3];
                    LDSM4(r, ad + FKT);
                    bl[nt2*2][0] = r[0]; bl[nt2*2+1][0] = r[1];
                    bl[nt2*2][1] = r[2]; bl[nt2*2+1][1] = r[3];
                }
                #pragma unroll
                for (int nt = 0; nt < 8; nt++) {
                    MMA16816(sacc[nt], qhi[kf], bh[nt]);
                    MMA16816(sacc[nt], qhi[kf], bl[nt]);
                    MMA16816(sacc[nt], qlo[kf], bh[nt]);
                }
            }

            if (kt * 64 + 63 > qrow0 + wid * 16) {
                #pragma unroll
                for (int nt = 0; nt < 8; nt++) {
                    int kc = kt * 64 + nt * 8 + 2 * (lane & 3);
                    if (kc     > qr0) sacc[nt][0] = -INFINITY;
                    if (kc + 1 > qr0) sacc[nt][1] = -INFINITY;
                    if (kc     > qr1) sacc[nt][2] = -INFINITY;
                    if (kc + 1 > qr1) sacc[nt][3] = -INFINITY;
                }
            }

            float mx0 = -INFINITY, mx1 = -INFINITY;
            #pragma unroll
            for (int nt = 0; nt < 8; nt++) {
                mx0 = fmaxf(mx0, fmaxf(sacc[nt][0], sacc[nt][1]));
                mx1 = fmaxf(mx1, fmaxf(sacc[nt][2], sacc[nt][3]));
            }
            #pragma unroll
            for (int o = 1; o <= 2; o <<= 1) {
                mx0 = fmaxf(mx0, __shfl_xor_sync(0xffffffffu, mx0, o));
                mx1 = fmaxf(mx1, __shfl_xor_sync(0xffffffffu, mx1, o));
            }
            float m0n = fmaxf(m0, mx0), m1n = fmaxf(m1, mx1);
            float c0 = __expf(m0 - m0n), c1 = __expf(m1 - m1n);
            float s0 = 0.f, s1 = 0.f;
            #pragma unroll
            for (int nt = 0; nt < 8; nt++) {
                sacc[nt][0] = __expf(sacc[nt][0] - m0n);
                sacc[nt][1] = __expf(sacc[nt][1] - m0n);
                sacc[nt][2] = __expf(sacc[nt][2] - m1n);
                sacc[nt][3] = __expf(sacc[nt][3] - m1n);
                s0 += sacc[nt][0] + sacc[nt][1];
                s1 += sacc[nt][2] + sacc[nt][3];
            }
            #pragma unroll
            for (int o = 1; o <= 2; o <<= 1) {
                s0 += __shfl_xor_sync(0xffffffffu, s0, o);
                s1 += __shfl_xor_sync(0xffffffffu, s1, o);
            }
            l0 = l0 * c0 + s0; l1 = l1 * c1 + s1;
            m0 = m0n; m1 = m1n;
            #pragma unroll
            for (int nt = 0; nt < 8; nt++) {
                oacc[nt][0] *= c0; oacc[nt][1] *= c0;
                oacc[nt][2] *= c1; oacc[nt][3] *= c1;
            }

            uint32_t phi[4][4], plo[4][4];
            #pragma unroll
            for (int kf = 0; kf < 4; kf++) {
                #pragma unroll
                for (int half = 0; half < 2; half++) {
                    float a = sacc[2*kf + half][0], bb = sacc[2*kf + half][1];
                    float cc = sacc[2*kf + half][2], dd = sacc[2*kf + half][3];
                    uint32_t ph0 = pack_bf16(a, bb), ph1 = pack_bf16(cc, dd);
                    phi[kf][half*2]   = ph0;
                    phi[kf][half*2+1] = ph1;
                    __nv_bfloat162 t0 = *(__nv_bfloat162*)&ph0;
                    __nv_bfloat162 t1 = *(__nv_bfloat162*)&ph1;
                    plo[kf][half*2]   = pack_bf16(a - __bfloat162float(t0.x),
                                                  bb - __bfloat162float(t0.y));
                    plo[kf][half*2+1] = pack_bf16(cc - __bfloat162float(t1.x),
                                                  dd - __bfloat162float(t1.y));
                }
            }

            #pragma unroll
            for (int kf = 0; kf < 4; kf++) {
                uint32_t vh[8][2], vl[8][2];
                #pragma unroll
                for (int nt2 = 0; nt2 < 4; nt2++) {
                    int vrow = kf * 16 + lrow;
                    int chunk = nt2 * 2 + lhalf;
                    uint32_t ad = Vb + vrow * 128 + ((chunk ^ (vrow & 7)) << 4);
                    uint32_t r[4];
                    LDSM4T(r, ad);
                    vh[nt2*2][0] = r[0]; vh[nt2*2][1] = r[1];
                    vh[nt2*2+1][0] = r[2]; vh[nt2*2+1][1] = r[3];
                    LDSM4T(r, ad + FKT);
                    vl[nt2*2][0] = r[0]; vl[nt2*2][1] = r[1];
                    vl[nt2*2+1][0] = r[2]; vl[nt2*2+1][1] = r[3];
                }
                #pragma unroll
                for (int nt = 0; nt < 8; nt++) {
                    MMA16816(oacc[nt], phi[kf], vh[nt]);
                    MMA16816(oacc[nt], phi[kf], vl[nt]);
                    MMA16816(oacc[nt], plo[kf], vh[nt]);
                }
            }
        }
    }

    float inv0 = 1.0f / l0, inv1 = 1.0f / l1;
    #pragma unroll
    for (int nt = 0; nt < 8; nt++) {
        int col = h * DH + nt * 8 + 2 * (lane & 3);
        {
            float v0 = oacc[nt][0] * inv0, v1 = oacc[nt][1] * inv0;
            size_t idx = (size_t)(b * TT + qr0) * DD + col;
            uint32_t hp = pack_bf16(v0, v1);
            __nv_bfloat162 t = *(__nv_bfloat162*)&hp;
            uint32_t lp = pack_bf16(v0 - __bfloat162float(t.x), v1 - __bfloat162float(t.y));
            *(uint32_t*)(g_aohi + idx) = hp;
            *(uint32_t*)(g_aolo + idx) = lp;
        }
        {
            float v0 = oacc[nt][2] * inv1, v1 = oacc[nt][3] * inv1;
            size_t idx = (size_t)(b * TT + qr1) * DD + col;
            uint32_t hp = pack_bf16(v0, v1);
            __nv_bfloat162 t = *(__nv_bfloat162*)&hp;
            uint32_t lp = pack_bf16(v0 - __bfloat162float(t.x), v1 - __bfloat162float(t.y));
            *(uint32_t*)(g_aohi + idx) = hp;
            *(uint32_t*)(g_aolo + idx) = lp;
        }
    }
}

// ---------------- launch -----------------------------------------------------
extern "C" void kernel_launch(void* const* d_in, const int* in_sizes, int n_in,
                              void* d_out, int out_size)
{
    const float* x    = (const float*)d_in[0];
    const float* cosT = (const float*)d_in[1];
    const float* sinT = (const float*)d_in[2];
    const float* Wq   = (const float*)d_in[3];
    const float* Wk   = (const float*)d_in[4];
    const float* Wv   = (const float*)d_in[5];
    const float* Wo   = (const float*)d_in[6];
    float* out = (float*)d_out;

    cudaFuncSetAttribute(k_gemm,      cudaFuncAttributeMaxDynamicSharedMemorySize, GSMEM);
    cudaFuncSetAttribute(k_flash_mma, cudaFuncAttributeMaxDynamicSharedMemorySize, FSMEM);

    void* p_swi;
    cudaGetSymbolAddress(&p_swi, g_swi);
    cudaMemsetAsync(p_swi, 0, 4 * DD * sizeof(int));

    // 1) quantize weights (col-max, then 2-slice int8 transpose) and X rows
    k_colmax<<<dim3(32, 4), 256>>>(Wq, Wk, Wv, Wo);
    k_wquant<<<dim3(32, 32, 4), dim3(32, 8)>>>(Wq, Wk, Wv, Wo);
    k_quant<<<BT / 8, 256>>>(x, 0);
    // 2) Q,K,V projections on int8 IMMA (fp32 out)
    k_gemm<<<dim3(DD / 128, BT / 128, 3), 256, GSMEM>>>(0, nullptr, -1);
    // 3) RoPE + bf16 hi/lo conversion (q pre-scaled by 1/8)
    k_rope_cvt<<<dim3((BT * HH * 8) / 256, 3), 256>>>(cosT, sinT);
    // 4) causal flash attention on bf16 HMMA -> g_aohi/g_aolo
    k_flash_mma<<<dim3(TT / 128, HH, BB), 256, FSMEM>>>();
    // 5) quantize attention output, output projection on int8 IMMA
    k_quant<<<BT / 8, 256>>>(nullptr, 1);
    k_gemm<<<dim3(DD / 128, BT / 128, 1), 256, GSMEM>>>(1, out, 3);
}

// round 14
// speedup vs baseline: 2.8013x; 2.8013x over previous
#include <cuda_runtime.h>
#include <cuda_fp16.h>
#include <stdint.h>
#include <math.h>

#define BB 4
#define TT 2048
#define DD 1024
#define HH 16
#define DH 64
#define BT (BB*TT)

// ---------------- scratch ----------------------------------------------------
__device__ float g_q [BT*DD];
__device__ float g_k [BT*DD];
__device__ float g_v [BT*DD];
__device__ __half g_xhi [BT*DD];
__device__ __half g_xlo [BT*DD];
__device__ __half g_aohi[BT*DD];
__device__ __half g_aolo[BT*DD];
__device__ __half g_qhi [BT*DD];
__device__ __half g_qlo [BT*DD];
__device__ __half g_kf  [BT*DD];
__device__ __half g_vf  [BT*DD];
__device__ __half g_wt  [4*DD*DD];   // transposed single-fp16 weights [w*1024+n][k]

// ---------------- PTX helpers ------------------------------------------------
static __device__ __forceinline__ uint32_t s2u(const void* p){
    uint32_t a;
    asm("{ .reg .u64 t; cvta.to.shared.u64 t, %1; cvt.u32.u64 %0, t; }" : "=r"(a) : "l"(p));
    return a;
}
static __device__ __forceinline__ void cpa16(uint32_t dst, const void* src){
    asm volatile("cp.async.cg.shared.global [%0], [%1], 16;" :: "r"(dst), "l"(src));
}
#define CP_COMMIT()  asm volatile("cp.async.commit_group;" ::: "memory")
#define CP_WAIT1()   asm volatile("cp.async.wait_group 1;" ::: "memory")
#define CP_WAIT0()   asm volatile("cp.async.wait_group 0;" ::: "memory")

#define LDSM4(r, addr) \
    asm volatile("ldmatrix.sync.aligned.m8n8.x4.shared.b16 {%0,%1,%2,%3}, [%4];" \
        : "=r"((r)[0]), "=r"((r)[1]), "=r"((r)[2]), "=r"((r)[3]) : "r"(addr))
#define LDSM4T(r, addr) \
    asm volatile("ldmatrix.sync.aligned.m8n8.x4.trans.shared.b16 {%0,%1,%2,%3}, [%4];" \
        : "=r"((r)[0]), "=r"((r)[1]), "=r"((r)[2]), "=r"((r)[3]) : "r"(addr))
#define MMAF16(d, a, b) \
    asm volatile("mma.sync.aligned.m16n8k16.row.col.f32.f16.f16.f32 " \
        "{%0,%1,%2,%3}, {%4,%5,%6,%7}, {%8,%9}, {%0,%1,%2,%3};" \
        : "+f"((d)[0]), "+f"((d)[1]), "+f"((d)[2]), "+f"((d)[3]) \
        : "r"((a)[0]), "r"((a)[1]), "r"((a)[2]), "r"((a)[3]), \
          "r"((b)[0]), "r"((b)[1]))

static __device__ __forceinline__ uint32_t pack_h2(float x, float y){
    __half2 t = __floats2half2_rn(x, y);
    return *(uint32_t*)&t;
}

// ---------------- conversion kernels ------------------------------------------
__global__ void k_split(const float* __restrict__ s)
{
    size_t i = ((size_t)blockIdx.x * 256 + threadIdx.x) * 4;
    float4 v = *(const float4*)(s + i);
    __half h0 = __float2half_rn(v.x), h1 = __float2half_rn(v.y);
    __half h2 = __float2half_rn(v.z), h3 = __float2half_rn(v.w);
    __half l0 = __float2half_rn(v.x - __half2float(h0));
    __half l1 = __float2half_rn(v.y - __half2float(h1));
    __half l2 = __float2half_rn(v.z - __half2float(h2));
    __half l3 = __float2half_rn(v.w - __half2float(h3));
    *(__half2*)(g_xhi + i)     = __halves2half2(h0, h1);
    *(__half2*)(g_xhi + i + 2) = __halves2half2(h2, h3);
    *(__half2*)(g_xlo + i)     = __halves2half2(l0, l1);
    *(__half2*)(g_xlo + i + 2) = __halves2half2(l2, l3);
}

__global__ void k_wcvt(const float* __restrict__ Wq, const float* __restrict__ Wk,
                       const float* __restrict__ Wv, const float* __restrict__ Wo)
{
    __shared__ float t[32][33];
    int z = blockIdx.z;
    const float* W = (z == 0) ? Wq : (z == 1) ? Wk : (z == 2) ? Wv : Wo;
    __half* wt = g_wt + (size_t)z * DD * DD;
    int tx = threadIdx.x, ty = threadIdx.y;
    #pragma unroll
    for (int i = 0; i < 4; i++) {
        int r = blockIdx.y * 32 + ty + i * 8;       // k
        int c = blockIdx.x * 32 + tx;               // n
        t[ty + i * 8][tx] = W[(size_t)r * DD + c];
    }
    __syncthreads();
    #pragma unroll
    for (int i = 0; i < 4; i++) {
        int n = blockIdx.x * 32 + ty + i * 8;
        int k = blockIdx.y * 32 + tx;
        wt[(size_t)n * DD + k] = __float2half_rn(t[tx][ty + i * 8]);
    }
}

// ---------------- fp16 2-term GEMM --------------------------------------------
// C = (Ahi+Alo) @ Wt^T, B single fp16. Block 128x128, BK=32, 3-stage cp.async,
// 8 warps (64x32), 2 MMAs per mma tile. 64B rows, swizzle chunk ^= (row>>1)&3.
#define TILEB (128*64)
#define STGB  (3*TILEB)             // Ahi, Alo, B = 24576
#define NSTG  3
#define GSMEM (NSTG*STGB)           // 73728

__global__ void __launch_bounds__(256, 1)
k_gemm(int asel, float* __restrict__ Cext, int wsel)
{
    extern __shared__ char smem[];
    const uint32_t sb0 = s2u(smem);
    const int tid  = threadIdx.x;
    const int lane = tid & 31, wid = tid >> 5;
    const int wm = wid >> 2, wn = wid & 3;
    const int m0 = blockIdx.y * 128, n0 = blockIdx.x * 128;

    const __half* Ahi = asel ? g_aohi : g_xhi;
    const __half* Alo = asel ? g_aolo : g_xlo;
    const int w = (wsel < 0) ? (int)blockIdx.z : wsel;
    float* C = (wsel < 0) ? (blockIdx.z == 0 ? g_q : (blockIdx.z == 1 ? g_k : g_v)) : Cext;
    const __half* B = g_wt + (size_t)w * DD * DD;

    auto load_stage = [&](int s, int kc) {
        const uint32_t st = sb0 + s * STGB;
        const int k0 = kc * 32;
        #pragma unroll
        for (int j = 0; j < 2; j++) {
            int e   = tid + j * 256;
            int row = e >> 2, c4 = e & 3;
            size_t ga = (size_t)(m0 + row) * DD + k0 + c4 * 8;
            size_t gb = (size_t)(n0 + row) * DD + k0 + c4 * 8;
            uint32_t so = row * 64 + ((c4 ^ ((row >> 1) & 3)) << 4);
            cpa16(st + so,             Ahi + ga);
            cpa16(st + TILEB + so,     Alo + ga);
            cpa16(st + 2*TILEB + so,   B + gb);
        }
        CP_COMMIT();
    };

    float acc[4][4][4] = {};
    const int lrow = lane & 15;
    const int swl  = (lrow >> 1) & 3;
    const int lhalf = lane >> 4;

    load_stage(0, 0);
    load_stage(1, 1);

    for (int kc = 0; kc < 32; kc++) {
        CP_WAIT1();
        __syncthreads();
        if (kc + 2 < 32) load_stage((kc + 2) % NSTG, kc + 2);
        else             CP_COMMIT();

        const uint32_t sA = sb0 + (kc % NSTG) * STGB;
        const uint32_t sB = sA + 2 * TILEB;

        #pragma unroll
        for (int kk = 0; kk < 2; kk++) {
            const int chunk = kk * 2 + lhalf;
            const uint32_t soff = lrow * 64 + ((chunk ^ swl) << 4);
            uint32_t ah[4][4], al[4][4];
            #pragma unroll
            for (int i = 0; i < 4; i++) {
                uint32_t ad = sA + (wm * 64 + i * 16) * 64 + soff;
                LDSM4(ah[i], ad);
                LDSM4(al[i], ad + TILEB);
            }
            uint32_t bfr[4][2];
            #pragma unroll
            for (int g = 0; g < 2; g++) {
                uint32_t bd = sB + (wn * 32 + g * 16) * 64 + soff;
                uint32_t r[4];
                LDSM4(r, bd);
                bfr[g*2][0] = r[0]; bfr[g*2+1][0] = r[1];
                bfr[g*2][1] = r[2]; bfr[g*2+1][1] = r[3];
            }
            #pragma unroll
            for (int i = 0; i < 4; i++)
                #pragma unroll
                for (int j = 0; j < 4; j++) {
                    MMAF16(acc[i][j], ah[i], bfr[j]);
                    MMAF16(acc[i][j], al[i], bfr[j]);
                }
        }
    }

    #pragma unroll
    for (int i = 0; i < 4; i++) {
        int row = m0 + wm * 64 + i * 16 + (lane >> 2);
        #pragma unroll
        for (int j = 0; j < 4; j++) {
            int col = n0 + wn * 32 + j * 8 + (lane & 3) * 2;
            *(float2*)(C + (size_t)row * DD + col)       = make_float2(acc[i][j][0], acc[i][j][1]);
            *(float2*)(C + (size_t)(row + 8) * DD + col) = make_float2(acc[i][j][2], acc[i][j][3]);
        }
    }
}

// ---------------- RoPE + conversion -------------------------------------------
// y=0: q (rope, x1/8) -> qhi/qlo ; y=1: k (rope) -> g_kf ; y=2: v -> g_vf
__global__ void k_rope_cvt(const float* __restrict__ cosT, const float* __restrict__ sinT)
{
    int n = blockIdx.x * blockDim.x + threadIdx.x;
    int y = blockIdx.y;
    const float* src = (y == 0) ? g_q : (y == 1) ? g_k : g_v;
    int i4   = (n & 7) * 4;
    int rest = n >> 3;
    int h    = rest & (HH - 1);
    int bt   = rest >> 4;
    int t    = bt & (TT - 1);

    size_t off = (size_t)bt * DD + h * DH;
    float4 x0 = *(const float4*)(src + off + i4);
    float4 x1 = *(const float4*)(src + off + i4 + 32);
    float4 y0, y1;
    if (y < 2) {
        float4 c0 = *(const float4*)(cosT + t * DH + i4);
        float4 s0 = *(const float4*)(sinT + t * DH + i4);
        float4 c1 = *(const float4*)(cosT + t * DH + i4 + 32);
        float4 s1 = *(const float4*)(sinT + t * DH + i4 + 32);
        y0.x = x0.x*c0.x - x1.x*s0.x;  y0.y = x0.y*c0.y - x1.y*s0.y;
        y0.z = x0.z*c0.z - x1.z*s0.z;  y0.w = x0.w*c0.w - x1.w*s0.w;
        y1.x = x1.x*c1.x + x0.x*s1.x;  y1.y = x1.y*c1.y + x0.y*s1.y;
        y1.z = x1.z*c1.z + x0.z*s1.z;  y1.w = x1.w*c1.w + x0.w*s1.w;
        if (y == 0) {
            y0.x *= 0.125f; y0.y *= 0.125f; y0.z *= 0.125f; y0.w *= 0.125f;
            y1.x *= 0.125f; y1.y *= 0.125f; y1.z *= 0.125f; y1.w *= 0.125f;
        }
    } else { y0 = x0; y1 = x1; }

    if (y == 0) {
        uint2 h0, h1, l0, l1;
        h0.x = pack_h2(y0.x, y0.y); h0.y = pack_h2(y0.z, y0.w);
        h1.x = pack_h2(y1.x, y1.y); h1.y = pack_h2(y1.z, y1.w);
        __half2 t0 = *(__half2*)&h0.x, t1 = *(__half2*)&h0.y;
        __half2 t2 = *(__half2*)&h1.x, t3 = *(__half2*)&h1.y;
        l0.x = pack_h2(y0.x - __half2float(t0.x), y0.y - __half2float(t0.y));
        l0.y = pack_h2(y0.z - __half2float(t1.x), y0.w - __half2float(t1.y));
        l1.x = pack_h2(y1.x - __half2float(t2.x), y1.y - __half2float(t2.y));
        l1.y = pack_h2(y1.z - __half2float(t3.x), y1.w - __half2float(t3.y));
        *(uint2*)(g_qhi + off + i4)      = h0;
        *(uint2*)(g_qhi + off + i4 + 32) = h1;
        *(uint2*)(g_qlo + off + i4)      = l0;
        *(uint2*)(g_qlo + off + i4 + 32) = l1;
    } else {
        __half* dst = (y == 1) ? g_kf : g_vf;
        uint2 h0, h1;
        h0.x = pack_h2(y0.x, y0.y); h0.y = pack_h2(y0.z, y0.w);
        h1.x = pack_h2(y1.x, y1.y); h1.y = pack_h2(y1.z, y1.w);
        *(uint2*)(dst + off + i4)      = h0;
        *(uint2*)(dst + off + i4 + 32) = h1;
    }
}

// ---------------- Flash attention (fp16 2-term) -------------------------------
// S = Qhi/Qlo x K-single (2 MMAs), PV = Phi/Plo x V-single (2 MMAs).
// Rows 128B, swizzle chunk ^= row&7.
#define FQT   (128*128)             // 16384 per Q term
#define FKT   (64*128)              // 8192 per K or V tile
#define FSTG  (2*FKT)               // K + V = 16384
#define FSMEM (2*FQT + 2*FSTG)      // 65536

__global__ void __launch_bounds__(256, 1) k_flash_mma()
{
    extern __shared__ char fsm[];
    const uint32_t sb = s2u(fsm);
    const int tid = threadIdx.x, lane = tid & 31, wid = tid >> 5;
    const int qt = (gridDim.x - 1) - blockIdx.x;
    const int h = blockIdx.y, b = blockIdx.z;
    const int qrow0 = qt * 128;
    const int nkt = 2 * qt + 2;
    const int lrow = lane & 15;
    const int sw7  = lane & 7;
    const int lhalf = lane >> 4;

    {
        #pragma unroll
        for (int j = 0; j < 4; j++) {
            int e = tid + j * 256;
            int row = e >> 3, c8 = e & 7;
            size_t g = (size_t)(b * TT + qrow0 + row) * DD + h * DH + c8 * 8;
            uint32_t so = row * 128 + ((c8 ^ (row & 7)) << 4);
            cpa16(sb + so,       g_qhi + g);
            cpa16(sb + FQT + so, g_qlo + g);
        }
    }
    auto load_kv = [&](int kt) {
        const uint32_t st = sb + 2 * FQT + (kt & 1) * FSTG;
        #pragma unroll
        for (int j = 0; j < 2; j++) {
            int e = tid + j * 256;
            int row = e >> 3, c8 = e & 7;
            size_t g = (size_t)(b * TT + kt * 64 + row) * DD + h * DH + c8 * 8;
            uint32_t so = row * 128 + ((c8 ^ (row & 7)) << 4);
            cpa16(st + so,       g_kf + g);
            cpa16(st + FKT + so, g_vf + g);
        }
    };
    load_kv(0);
    CP_COMMIT();

    uint32_t qhi[4][4], qlo[4][4];
    float oacc[8][4] = {};
    float m0 = -INFINITY, m1 = -INFINITY, l0 = 0.f, l1 = 0.f;
    const int qr0 = qrow0 + wid * 16 + (lane >> 2);
    const int qr1 = qr0 + 8;

    for (int kt = 0; kt < nkt; kt++) {
        CP_WAIT0();
        __syncthreads();
        if (kt == 0) {
            #pragma unroll
            for (int kf = 0; kf < 4; kf++) {
                int chunk = kf * 2 + lhalf;
                uint32_t ad = sb + (wid * 16 + lrow) * 128 + ((chunk ^ sw7) << 4);
                LDSM4(qhi[kf], ad);
                LDSM4(qlo[kf], ad + FQT);
            }
        }
        if (kt + 1 < nkt) { load_kv(kt + 1); CP_COMMIT(); }

        const bool active = (kt * 64) <= (qrow0 + wid * 16 + 15);
        if (active) {
            const uint32_t Kb = sb + 2 * FQT + (kt & 1) * FSTG;
            const uint32_t Vb = Kb + FKT;

            float sacc[8][4] = {};
            #pragma unroll
            for (int kf = 0; kf < 4; kf++) {
                const int chunk = kf * 2 + lhalf;
                uint32_t bh[8][2];
                #pragma unroll
                for (int nt2 = 0; nt2 < 4; nt2++) {
                    uint32_t ad = Kb + (nt2 * 16 + lrow) * 128 + ((chunk ^ sw7) << 4);
                    uint32_t r[4];
                    LDSM4(r, ad);
                    bh[nt2*2][0] = r[0]; bh[nt2*2+1][0] = r[1];
                    bh[nt2*2][1] = r[2]; bh[nt2*2+1][1] = r[3];
                }
                #pragma unroll
                for (int nt = 0; nt < 8; nt++) {
                    MMAF16(sacc[nt], qhi[kf], bh[nt]);
                    MMAF16(sacc[nt], qlo[kf], bh[nt]);
                }
            }

            if (kt * 64 + 63 > qrow0 + wid * 16) {
                #pragma unroll
                for (int nt = 0; nt < 8; nt++) {
                    int kc = kt * 64 + nt * 8 + 2 * (lane & 3);
                    if (kc     > qr0) sacc[nt][0] = -INFINITY;
                    if (kc + 1 > qr0) sacc[nt][1] = -INFINITY;
                    if (kc     > qr1) sacc[nt][2] = -INFINITY;
                    if (kc + 1 > qr1) sacc[nt][3] = -INFINITY;
                }
            }

            float mx0 = -INFINITY, mx1 = -INFINITY;
            #pragma unroll
            for (int nt = 0; nt < 8; nt++) {
                mx0 = fmaxf(mx0, fmaxf(sacc[nt][0], sacc[nt][1]));
                mx1 = fmaxf(mx1, fmaxf(sacc[nt][2], sacc[nt][3]));
            }
            #pragma unroll
            for (int o = 1; o <= 2; o <<= 1) {
                mx0 = fmaxf(mx0, __shfl_xor_sync(0xffffffffu, mx0, o));
                mx1 = fmaxf(mx1, __shfl_xor_sync(0xffffffffu, mx1, o));
            }
            float m0n = fmaxf(m0, mx0), m1n = fmaxf(m1, mx1);
            float c0 = __expf(m0 - m0n), c1 = __expf(m1 - m1n);
            float s0 = 0.f, s1 = 0.f;
            #pragma unroll
            for (int nt = 0; nt < 8; nt++) {
                sacc[nt][0] = __expf(sacc[nt][0] - m0n);
                sacc[nt][1] = __expf(sacc[nt][1] - m0n);
                sacc[nt][2] = __expf(sacc[nt][2] - m1n);
                sacc[nt][3] = __expf(sacc[nt][3] - m1n);
                s0 += sacc[nt][0] + sacc[nt][1];
                s1 += sacc[nt][2] + sacc[nt][3];
            }
            #pragma unroll
            for (int o = 1; o <= 2; o <<= 1) {
                s0 += __shfl_xor_sync(0xffffffffu, s0, o);
                s1 += __shfl_xor_sync(0xffffffffu, s1, o);
            }
            l0 = l0 * c0 + s0; l1 = l1 * c1 + s1;
            m0 = m0n; m1 = m1n;
            #pragma unroll
            for (int nt = 0; nt < 8; nt++) {
                oacc[nt][0] *= c0; oacc[nt][1] *= c0;
                oacc[nt][2] *= c1; oacc[nt][3] *= c1;
            }

            uint32_t phi[4][4], plo[4][4];
            #pragma unroll
            for (int kf = 0; kf < 4; kf++) {
                #pragma unroll
                for (int half = 0; half < 2; half++) {
                    float a = sacc[2*kf + half][0], bb = sacc[2*kf + half][1];
                    float cc = sacc[2*kf + half][2], dd = sacc[2*kf + half][3];
                    uint32_t ph0 = pack_h2(a, bb), ph1 = pack_h2(cc, dd);
                    phi[kf][half*2]   = ph0;
                    phi[kf][half*2+1] = ph1;
                    __half2 t0 = *(__half2*)&ph0;
                    __half2 t1 = *(__half2*)&ph1;
                    plo[kf][half*2]   = pack_h2(a - __half2float(t0.x),
                                                bb - __half2float(t0.y));
                    plo[kf][half*2+1] = pack_h2(cc - __half2float(t1.x),
                                                dd - __half2float(t1.y));
                }
            }

            #pragma unroll
            for (int kf = 0; kf < 4; kf++) {
                uint32_t vh[8][2];
                #pragma unroll
                for (int nt2 = 0; nt2 < 4; nt2++) {
                    int vrow = kf * 16 + lrow;
                    int chunk = nt2 * 2 + lhalf;
                    uint32_t ad = Vb + vrow * 128 + ((chunk ^ (vrow & 7)) << 4);
                    uint32_t r[4];
                    LDSM4T(r, ad);
                    vh[nt2*2][0] = r[0]; vh[nt2*2][1] = r[1];
                    vh[nt2*2+1][0] = r[2]; vh[nt2*2+1][1] = r[3];
                }
                #pragma unroll
                for (int nt = 0; nt < 8; nt++) {
                    MMAF16(oacc[nt], phi[kf], vh[nt]);
                    MMAF16(oacc[nt], plo[kf], vh[nt]);
                }
            }
        }
    }

    float inv0 = 1.0f / l0, inv1 = 1.0f / l1;
    #pragma unroll
    for (int nt = 0; nt < 8; nt++) {
        int col = h * DH + nt * 8 + 2 * (lane & 3);
        {
            float v0 = oacc[nt][0] * inv0, v1 = oacc[nt][1] * inv0;
            size_t idx = (size_t)(b * TT + qr0) * DD + col;
            uint32_t hp = pack_h2(v0, v1);
            __half2 t = *(__half2*)&hp;
            uint32_t lp = pack_h2(v0 - __half2float(t.x), v1 - __half2float(t.y));
            *(uint32_t*)(g_aohi + idx) = hp;
            *(uint32_t*)(g_aolo + idx) = lp;
        }
        {
            float v0 = oacc[nt][2] * inv1, v1 = oacc[nt][3] * inv1;
            size_t idx = (size_t)(b * TT + qr1) * DD + col;
            uint32_t hp = pack_h2(v0, v1);
            __half2 t = *(__half2*)&hp;
            uint32_t lp = pack_h2(v0 - __half2float(t.x), v1 - __half2float(t.y));
            *(uint32_t*)(g_aohi + idx) = hp;
            *(uint32_t*)(g_aolo + idx) = lp;
        }
    }
}

// ---------------- launch -----------------------------------------------------
extern "C" void kernel_launch(void* const* d_in, const int* in_sizes, int n_in,
                              void* d_out, int out_size)
{
    const float* x    = (const float*)d_in[0];
    const float* cosT = (const float*)d_in[1];
    const float* sinT = (const float*)d_in[2];
    const float* Wq   = (const float*)d_in[3];
    const float* Wk   = (const float*)d_in[4];
    const float* Wv   = (const float*)d_in[5];
    const float* Wo   = (const float*)d_in[6];
    float* out = (float*)d_out;

    cudaFuncSetAttribute(k_gemm,      cudaFuncAttributeMaxDynamicSharedMemorySize, GSMEM);
    cudaFuncSetAttribute(k_flash_mma, cudaFuncAttributeMaxDynamicSharedMemorySize, FSMEM);

    // 1) split X into hi/lo fp16; transpose+convert weights to single fp16
    k_split<<<(BT * DD) / (256 * 4), 256>>>(x);
    k_wcvt<<<dim3(32, 32, 4), dim3(32, 8)>>>(Wq, Wk, Wv, Wo);
    // 2) Q,K,V projections: (Xhi+Xlo) x Wf, 2 MMAs/tile
    k_gemm<<<dim3(DD / 128, BT / 128, 3), 256, GSMEM>>>(0, nullptr, -1);
    // 3) RoPE + conversion: q -> hi/lo fp16 (x1/8), k,v -> single fp16
    k_rope_cvt<<<dim3((BT * HH * 8) / 256, 3), 256>>>(cosT, sinT);
    // 4) causal flash attention, fp16 2-term -> g_aohi/g_aolo
    k_flash_mma<<<dim3(TT / 128, HH, BB), 256, FSMEM>>>();
    // 5) output projection: (AOhi+AOlo) x Wf
    k_gemm<<<dim3(DD / 128, BT / 128, 1), 256, GSMEM>>>(1, out, 3);
}

// round 16
// speedup vs baseline: 3.8020x; 1.3572x over previous
#include <cuda_runtime.h>
#include <cuda_fp16.h>
#include <stdint.h>
#include <math.h>

#define BB 4
#define TT 2048
#define DD 1024
#define HH 16
#define DH 64
#define BT (BB*TT)

// ---------------- scratch ----------------------------------------------------
__device__ float g_q [BT*DD];
__device__ float g_k [BT*DD];
__device__ float g_v [BT*DD];
__device__ __half g_xf  [BT*DD];
__device__ __half g_aof [BT*DD];
__device__ __half g_qhi [BT*DD];
__device__ __half g_qlo [BT*DD];
__device__ __half g_kf  [BT*DD];
__device__ __half g_vf  [BT*DD];
__device__ __half g_wt  [4*DD*DD];   // transposed single-fp16 weights [w*1024+n][k]

// ---------------- PTX helpers ------------------------------------------------
static __device__ __forceinline__ uint32_t s2u(const void* p){
    uint32_t a;
    asm("{ .reg .u64 t; cvta.to.shared.u64 t, %1; cvt.u32.u64 %0, t; }" : "=r"(a) : "l"(p));
    return a;
}
static __device__ __forceinline__ void cpa16(uint32_t dst, const void* src){
    asm volatile("cp.async.cg.shared.global [%0], [%1], 16;" :: "r"(dst), "l"(src));
}
#define CP_COMMIT()  asm volatile("cp.async.commit_group;" ::: "memory")
#define CP_WAIT1()   asm volatile("cp.async.wait_group 1;" ::: "memory")
#define CP_WAIT0()   asm volatile("cp.async.wait_group 0;" ::: "memory")

#define LDSM4(r, addr) \
    asm volatile("ldmatrix.sync.aligned.m8n8.x4.shared.b16 {%0,%1,%2,%3}, [%4];" \
        : "=r"((r)[0]), "=r"((r)[1]), "=r"((r)[2]), "=r"((r)[3]) : "r"(addr))
#define LDSM4T(r, addr) \
    asm volatile("ldmatrix.sync.aligned.m8n8.x4.trans.shared.b16 {%0,%1,%2,%3}, [%4];" \
        : "=r"((r)[0]), "=r"((r)[1]), "=r"((r)[2]), "=r"((r)[3]) : "r"(addr))
#define MMAF16(d, a, b) \
    asm volatile("mma.sync.aligned.m16n8k16.row.col.f32.f16.f16.f32 " \
        "{%0,%1,%2,%3}, {%4,%5,%6,%7}, {%8,%9}, {%0,%1,%2,%3};" \
        : "+f"((d)[0]), "+f"((d)[1]), "+f"((d)[2]), "+f"((d)[3]) \
        : "r"((a)[0]), "r"((a)[1]), "r"((a)[2]), "r"((a)[3]), \
          "r"((b)[0]), "r"((b)[1]))

static __device__ __forceinline__ uint32_t pack_h2(float x, float y){
    __half2 t = __floats2half2_rn(x, y);
    return *(uint32_t*)&t;
}

// ---------------- conversion kernels ------------------------------------------
__global__ void k_xcvt(const float* __restrict__ s)
{
    size_t i = ((size_t)blockIdx.x * 256 + threadIdx.x) * 4;
    float4 v = *(const float4*)(s + i);
    *(__half2*)(g_xf + i)     = __floats2half2_rn(v.x, v.y);
    *(__half2*)(g_xf + i + 2) = __floats2half2_rn(v.z, v.w);
}

__global__ void k_wcvt(const float* __restrict__ Wq, const float* __restrict__ Wk,
                       const float* __restrict__ Wv, const float* __restrict__ Wo)
{
    __shared__ float t[32][33];
    int z = blockIdx.z;
    const float* W = (z == 0) ? Wq : (z == 1) ? Wk : (z == 2) ? Wv : Wo;
    __half* wt = g_wt + (size_t)z * DD * DD;
    int tx = threadIdx.x, ty = threadIdx.y;
    #pragma unroll
    for (int i = 0; i < 4; i++) {
        int r = blockIdx.y * 32 + ty + i * 8;       // k
        int c = blockIdx.x * 32 + tx;               // n
        t[ty + i * 8][tx] = W[(size_t)r * DD + c];
    }
    __syncthreads();
    #pragma unroll
    for (int i = 0; i < 4; i++) {
        int n = blockIdx.x * 32 + ty + i * 8;
        int k = blockIdx.y * 32 + tx;
        wt[(size_t)n * DD + k] = __float2half_rn(t[tx][ty + i * 8]);
    }
}

// ---------------- fp16 single-term GEMM ---------------------------------------
// C = A @ Wt^T, both single fp16. Block 128x128, BK=32, 3-stage cp.async,
// 8 warps (64x32), 1 MMA per mma tile. 64B rows, swizzle chunk ^= (row>>1)&3.
// 48KB smem + <=128 regs -> 2 CTAs/SM (4 warps/SMSP).
#define TILEB (128*64)
#define STGB  (2*TILEB)             // A, B = 16384
#define NSTG  3
#define GSMEM (NSTG*STGB)           // 49152

__global__ void __launch_bounds__(256, 2)
k_gemm(int asel, float* __restrict__ Cext, int wsel)
{
    extern __shared__ char smem[];
    const uint32_t sb0 = s2u(smem);
    const int tid  = threadIdx.x;
    const int lane = tid & 31, wid = tid >> 5;
    const int wm = wid >> 2, wn = wid & 3;
    const int m0 = blockIdx.y * 128, n0 = blockIdx.x * 128;

    const __half* A = asel ? g_aof : g_xf;
    const int w = (wsel < 0) ? (int)blockIdx.z : wsel;
    float* C = (wsel < 0) ? (blockIdx.z == 0 ? g_q : (blockIdx.z == 1 ? g_k : g_v)) : Cext;
    const __half* B = g_wt + (size_t)w * DD * DD;

    auto load_stage = [&](int s, int kc) {
        const uint32_t st = sb0 + s * STGB;
        const int k0 = kc * 32;
        #pragma unroll
        for (int j = 0; j < 2; j++) {
            int e   = tid + j * 256;
            int row = e >> 2, c4 = e & 3;
            size_t ga = (size_t)(m0 + row) * DD + k0 + c4 * 8;
            size_t gb = (size_t)(n0 + row) * DD + k0 + c4 * 8;
            uint32_t so = row * 64 + ((c4 ^ ((row >> 1) & 3)) << 4);
            cpa16(st + so,         A + ga);
            cpa16(st + TILEB + so, B + gb);
        }
        CP_COMMIT();
    };

    float acc[4][4][4] = {};
    const int lrow = lane & 15;
    const int swl  = (lrow >> 1) & 3;
    const int lhalf = lane >> 4;

    load_stage(0, 0);
    load_stage(1, 1);

    for (int kc = 0; kc < 32; kc++) {
        CP_WAIT1();
        __syncthreads();
        if (kc + 2 < 32) load_stage((kc + 2) % NSTG, kc + 2);
        else             CP_COMMIT();

        const uint32_t sA = sb0 + (kc % NSTG) * STGB;
        const uint32_t sB = sA + TILEB;

        #pragma unroll
        for (int kk = 0; kk < 2; kk++) {
            const int chunk = kk * 2 + lhalf;
            const uint32_t soff = lrow * 64 + ((chunk ^ swl) << 4);
            uint32_t ah[4][4];
            #pragma unroll
            for (int i = 0; i < 4; i++) {
                uint32_t ad = sA + (wm * 64 + i * 16) * 64 + soff;
                LDSM4(ah[i], ad);
            }
            uint32_t bfr[4][2];
            #pragma unroll
            for (int g = 0; g < 2; g++) {
                uint32_t bd = sB + (wn * 32 + g * 16) * 64 + soff;
                uint32_t r[4];
                LDSM4(r, bd);
                bfr[g*2][0] = r[0]; bfr[g*2+1][0] = r[1];
                bfr[g*2][1] = r[2]; bfr[g*2+1][1] = r[3];
            }
            #pragma unroll
            for (int i = 0; i < 4; i++)
                #pragma unroll
                for (int j = 0; j < 4; j++)
                    MMAF16(acc[i][j], ah[i], bfr[j]);
        }
    }

    #pragma unroll
    for (int i = 0; i < 4; i++) {
        int row = m0 + wm * 64 + i * 16 + (lane >> 2);
        #pragma unroll
        for (int j = 0; j < 4; j++) {
            int col = n0 + wn * 32 + j * 8 + (lane & 3) * 2;
            *(float2*)(C + (size_t)row * DD + col)       = make_float2(acc[i][j][0], acc[i][j][1]);
            *(float2*)(C + (size_t)(row + 8) * DD + col) = make_float2(acc[i][j][2], acc[i][j][3]);
        }
    }
}

// ---------------- RoPE + conversion -------------------------------------------
// y=0: q (rope, x1/8) -> qhi/qlo ; y=1: k (rope) -> g_kf ; y=2: v -> g_vf
__global__ void k_rope_cvt(const float* __restrict__ cosT, const float* __restrict__ sinT)
{
    int n = blockIdx.x * blockDim.x + threadIdx.x;
    int y = blockIdx.y;
    const float* src = (y == 0) ? g_q : (y == 1) ? g_k : g_v;
    int i4   = (n & 7) * 4;
    int rest = n >> 3;
    int h    = rest & (HH - 1);
    int bt   = rest >> 4;
    int t    = bt & (TT - 1);

    size_t off = (size_t)bt * DD + h * DH;
    float4 x0 = *(const float4*)(src + off + i4);
    float4 x1 = *(const float4*)(src + off + i4 + 32);
    float4 y0, y1;
    if (y < 2) {
        float4 c0 = *(const float4*)(cosT + t * DH + i4);
        float4 s0 = *(const float4*)(sinT + t * DH + i4);
        float4 c1 = *(const float4*)(cosT + t * DH + i4 + 32);
        float4 s1 = *(const float4*)(sinT + t * DH + i4 + 32);
        y0.x = x0.x*c0.x - x1.x*s0.x;  y0.y = x0.y*c0.y - x1.y*s0.y;
        y0.z = x0.z*c0.z - x1.z*s0.z;  y0.w = x0.w*c0.w - x1.w*s0.w;
        y1.x = x1.x*c1.x + x0.x*s1.x;  y1.y = x1.y*c1.y + x0.y*s1.y;
        y1.z = x1.z*c1.z + x0.z*s1.z;  y1.w = x1.w*c1.w + x0.w*s1.w;
        if (y == 0) {
            y0.x *= 0.125f; y0.y *= 0.125f; y0.z *= 0.125f; y0.w *= 0.125f;
            y1.x *= 0.125f; y1.y *= 0.125f; y1.z *= 0.125f; y1.w *= 0.125f;
        }
    } else { y0 = x0; y1 = x1; }

    if (y == 0) {
        uint2 h0, h1, l0, l1;
        h0.x = pack_h2(y0.x, y0.y); h0.y = pack_h2(y0.z, y0.w);
        h1.x = pack_h2(y1.x, y1.y); h1.y = pack_h2(y1.z, y1.w);
        __half2 t0 = *(__half2*)&h0.x, t1 = *(__half2*)&h0.y;
        __half2 t2 = *(__half2*)&h1.x, t3 = *(__half2*)&h1.y;
        l0.x = pack_h2(y0.x - __half2float(t0.x), y0.y - __half2float(t0.y));
        l0.y = pack_h2(y0.z - __half2float(t1.x), y0.w - __half2float(t1.y));
        l1.x = pack_h2(y1.x - __half2float(t2.x), y1.y - __half2float(t2.y));
        l1.y = pack_h2(y1.z - __half2float(t3.x), y1.w - __half2float(t3.y));
        *(uint2*)(g_qhi + off + i4)      = h0;
        *(uint2*)(g_qhi + off + i4 + 32) = h1;
        *(uint2*)(g_qlo + off + i4)      = l0;
        *(uint2*)(g_qlo + off + i4 + 32) = l1;
    } else {
        __half* dst = (y == 1) ? g_kf : g_vf;
        uint2 h0, h1;
        h0.x = pack_h2(y0.x, y0.y); h0.y = pack_h2(y0.z, y0.w);
        h1.x = pack_h2(y1.x, y1.y); h1.y = pack_h2(y1.z, y1.w);
        *(uint2*)(dst + off + i4)      = h0;
        *(uint2*)(dst + off + i4 + 32) = h1;
    }
}

// ---------------- Flash attention (fp16 2-term) -------------------------------
// S = Qhi/Qlo x K-single (2 MMAs), PV = Phi/Plo x V-single (2 MMAs).
// Rows 128B, swizzle chunk ^= row&7. Epilogue writes single-fp16 AO.
#define FQT   (128*128)             // 16384 per Q term
#define FKT   (64*128)              // 8192 per K or V tile
#define FSTG  (2*FKT)               // K + V = 16384
#define FSMEM (2*FQT + 2*FSTG)      // 65536

__global__ void __launch_bounds__(256, 1) k_flash_mma()
{
    extern __shared__ char fsm[];
    const uint32_t sb = s2u(fsm);
    const int tid = threadIdx.x, lane = tid & 31, wid = tid >> 5;
    const int qt = (gridDim.x - 1) - blockIdx.x;
    const int h = blockIdx.y, b = blockIdx.z;
    const int qrow0 = qt * 128;
    const int nkt = 2 * qt + 2;
    const int lrow = lane & 15;
    const int sw7  = lane & 7;
    const int lhalf = lane >> 4;

    {
        #pragma unroll
        for (int j = 0; j < 4; j++) {
            int e = tid + j * 256;
            int row = e >> 3, c8 = e & 7;
            size_t g = (size_t)(b * TT + qrow0 + row) * DD + h * DH + c8 * 8;
            uint32_t so = row * 128 + ((c8 ^ (row & 7)) << 4);
            cpa16(sb + so,       g_qhi + g);
            cpa16(sb + FQT + so, g_qlo + g);
        }
    }
    auto load_kv = [&](int kt) {
        const uint32_t st = sb + 2 * FQT + (kt & 1) * FSTG;
        #pragma unroll
        for (int j = 0; j < 2; j++) {
            int e = tid + j * 256;
            int row = e >> 3, c8 = e & 7;
            size_t g = (size_t)(b * TT + kt * 64 + row) * DD + h * DH + c8 * 8;
            uint32_t so = row * 128 + ((c8 ^ (row & 7)) << 4);
            cpa16(st + so,       g_kf + g);
            cpa16(st + FKT + so, g_vf + g);
        }
    };
    load_kv(0);
    CP_COMMIT();

    uint32_t qhi[4][4], qlo[4][4];
    float oacc[8][4] = {};
    float m0 = -INFINITY, m1 = -INFINITY, l0 = 0.f, l1 = 0.f;
    const int qr0 = qrow0 + wid * 16 + (lane >> 2);
    const int qr1 = qr0 + 8;

    for (int kt = 0; kt < nkt; kt++) {
        CP_WAIT0();
        __syncthreads();
        if (kt == 0) {
            #pragma unroll
            for (int kf = 0; kf < 4; kf++) {
                int chunk = kf * 2 + lhalf;
                uint32_t ad = sb + (wid * 16 + lrow) * 128 + ((chunk ^ sw7) << 4);
                LDSM4(qhi[kf], ad);
                LDSM4(qlo[kf], ad + FQT);
            }
        }
        if (kt + 1 < nkt) { load_kv(kt + 1); CP_COMMIT(); }

        const bool active = (kt * 64) <= (qrow0 + wid * 16 + 15);
        if (active) {
            const uint32_t Kb = sb + 2 * FQT + (kt & 1) * FSTG;
            const uint32_t Vb = Kb + FKT;

            float sacc[8][4] = {};
            #pragma unroll
            for (int kf = 0; kf < 4; kf++) {
                const int chunk = kf * 2 + lhalf;
                uint32_t bh[8][2];
                #pragma unroll
                for (int nt2 = 0; nt2 < 4; nt2++) {
                    uint32_t ad = Kb + (nt2 * 16 + lrow) * 128 + ((chunk ^ sw7) << 4);
                    uint32_t r[4];
                    LDSM4(r, ad);
                    bh[nt2*2][0] = r[0]; bh[nt2*2+1][0] = r[1];
                    bh[nt2*2][1] = r[2]; bh[nt2*2+1][1] = r[3];
                }
                #pragma unroll
                for (int nt = 0; nt < 8; nt++) {
                    MMAF16(sacc[nt], qhi[kf], bh[nt]);
                    MMAF16(sacc[nt], qlo[kf], bh[nt]);
                }
            }

            if (kt * 64 + 63 > qrow0 + wid * 16) {
                #pragma unroll
                for (int nt = 0; nt < 8; nt++) {
                    int kc = kt * 64 + nt * 8 + 2 * (lane & 3);
                    if (kc     > qr0) sacc[nt][0] = -INFINITY;
                    if (kc + 1 > qr0) sacc[nt][1] = -INFINITY;
                    if (kc     > qr1) sacc[nt][2] = -INFINITY;
                    if (kc + 1 > qr1) sacc[nt][3] = -INFINITY;
                }
            }

            float mx0 = -INFINITY, mx1 = -INFINITY;
            #pragma unroll
            for (int nt = 0; nt < 8; nt++) {
                mx0 = fmaxf(mx0, fmaxf(sacc[nt][0], sacc[nt][1]));
                mx1 = fmaxf(mx1, fmaxf(sacc[nt][2], sacc[nt][3]));
            }
            #pragma unroll
            for (int o = 1; o <= 2; o <<= 1) {
                mx0 = fmaxf(mx0, __shfl_xor_sync(0xffffffffu, mx0, o));
                mx1 = fmaxf(mx1, __shfl_xor_sync(0xffffffffu, mx1, o));
            }
            float m0n = fmaxf(m0, mx0), m1n = fmaxf(m1, mx1);
            float c0 = __expf(m0 - m0n), c1 = __expf(m1 - m1n);
            float s0 = 0.f, s1 = 0.f;
            #pragma unroll
            for (int nt = 0; nt < 8; nt++) {
                sacc[nt][0] = __expf(sacc[nt][0] - m0n);
                sacc[nt][1] = __expf(sacc[nt][1] - m0n);
                sacc[nt][2] = __expf(sacc[nt][2] - m1n);
                sacc[nt][3] = __expf(sacc[nt][3] - m1n);
                s0 += sacc[nt][0] + sacc[nt][1];
                s1 += sacc[nt][2] + sacc[nt][3];
            }
            #pragma unroll
            for (int o = 1; o <= 2; o <<= 1) {
                s0 += __shfl_xor_sync(0xffffffffu, s0, o);
                s1 += __shfl_xor_sync(0xffffffffu, s1, o);
            }
            l0 = l0 * c0 + s0; l1 = l1 * c1 + s1;
            m0 = m0n; m1 = m1n;
            #pragma unroll
            for (int nt = 0; nt < 8; nt++) {
                oacc[nt][0] *= c0; oacc[nt][1] *= c0;
                oacc[nt][2] *= c1; oacc[nt][3] *= c1;
            }

            uint32_t phi[4][4], plo[4][4];
            #pragma unroll
            for (int kf = 0; kf < 4; kf++) {
                #pragma unroll
                for (int half = 0; half < 2; half++) {
                    float a = sacc[2*kf + half][0], bb = sacc[2*kf + half][1];
                    float cc = sacc[2*kf + half][2], dd = sacc[2*kf + half][3];
                    uint32_t ph0 = pack_h2(a, bb), ph1 = pack_h2(cc, dd);
                    phi[kf][half*2]   = ph0;
                    phi[kf][half*2+1] = ph1;
                    __half2 t0 = *(__half2*)&ph0;
                    __half2 t1 = *(__half2*)&ph1;
                    plo[kf][half*2]   = pack_h2(a - __half2float(t0.x),
                                                bb - __half2float(t0.y));
                    plo[kf][half*2+1] = pack_h2(cc - __half2float(t1.x),
                                                dd - __half2float(t1.y));
                }
            }

            #pragma unroll
            for (int kf = 0; kf < 4; kf++) {
                uint32_t vh[8][2];
                #pragma unroll
                for (int nt2 = 0; nt2 < 4; nt2++) {
                    int vrow = kf * 16 + lrow;
                    int chunk = nt2 * 2 + lhalf;
                    uint32_t ad = Vb + vrow * 128 + ((chunk ^ (vrow & 7)) << 4);
                    uint32_t r[4];
                    LDSM4T(r, ad);
                    vh[nt2*2][0] = r[0]; vh[nt2*2][1] = r[1];
                    vh[nt2*2+1][0] = r[2]; vh[nt2*2+1][1] = r[3];
                }
                #pragma unroll
                for (int nt = 0; nt < 8; nt++) {
                    MMAF16(oacc[nt], phi[kf], vh[nt]);
                    MMAF16(oacc[nt], plo[kf], vh[nt]);
                }
            }
        }
    }

    float inv0 = 1.0f / l0, inv1 = 1.0f / l1;
    #pragma unroll
    for (int nt = 0; nt < 8; nt++) {
        int col = h * DH + nt * 8 + 2 * (lane & 3);
        *(uint32_t*)(g_aof + (size_t)(b * TT + qr0) * DD + col)
            = pack_h2(oacc[nt][0] * inv0, oacc[nt][1] * inv0);
        *(uint32_t*)(g_aof + (size_t)(b * TT + qr1) * DD + col)
            = pack_h2(oacc[nt][2] * inv1, oacc[nt][3] * inv1);
    }
}

// ---------------- launch -----------------------------------------------------
extern "C" void kernel_launch(void* const* d_in, const int* in_sizes, int n_in,
                              void* d_out, int out_size)
{
    const float* x    = (const float*)d_in[0];
    const float* cosT = (const float*)d_in[1];
    const float* sinT = (const float*)d_in[2];
    const float* Wq   = (const float*)d_in[3];
    const float* Wk   = (const float*)d_in[4];
    const float* Wv   = (const float*)d_in[5];
    const float* Wo   = (const float*)d_in[6];
    float* out = (float*)d_out;

    cudaFuncSetAttribute(k_gemm,      cudaFuncAttributeMaxDynamicSharedMemorySize, GSMEM);
    cudaFuncSetAttribute(k_flash_mma, cudaFuncAttributeMaxDynamicSharedMemorySize, FSMEM);

    // 1) convert X + weights to single fp16 (weights transposed)
    k_xcvt<<<(BT * DD) / (256 * 4), 256>>>(x);
    k_wcvt<<<dim3(32, 32, 4), dim3(32, 8)>>>(Wq, Wk, Wv, Wo);
    // 2) Q,K,V projections: single-fp16 x single-fp16, 1 MMA/tile
    k_gemm<<<dim3(DD / 128, BT / 128, 3), 256, GSMEM>>>(0, nullptr, -1);
    // 3) RoPE + conversion: q -> hi/lo fp16 (x1/8), k,v -> single fp16
    k_rope_cvt<<<dim3((BT * HH * 8) / 256, 3), 256>>>(cosT, sinT);
    // 4) causal flash attention, fp16 2-term -> g_aof (single)
    k_flash_mma<<<dim3(TT / 128, HH, BB), 256, FSMEM>>>();
    // 5) output projection: single x single
    k_gemm<<<dim3(DD / 128, BT / 128, 1), 256, GSMEM>>>(1, out, 3);
}